// round 15
// baseline (speedup 1.0000x reference)
#include <cuda_runtime.h>
#include <cuda_fp16.h>
#include <cstdint>

// B=2,H=16,S=2048,D=64 fp32 attention; scale=1/sqrt(2048) AFTER masked_fill(-1e10).
// Logits bounded -> exp without max-subtraction; masked -> p=0.
// Round 15: R12 math, but 64-thread CTAs (BM=64 = 2 warps x 32 rows, still
// 2 m-tiles/warp) at 4 CTAs/SM: barrier alignment sets halve, per-SMSP warp
// streams stay 2 but fully independent. Pre-pass fused (cvt+mask scan).
#define SEQ 2048
#define DH  64
#define BM  64          // 2 warps x 32 rows
#define BN  64
#define NT  (SEQ/BN)
#define SH  72

#define K0H 0
#define K1H (64*SH)
#define V0H (2*64*SH)
#define V1H (3*64*SH)
#define SMEM_BYTES (4*64*SH*2)   // 36864 B per CTA

#define NELEM (2*16*2048*64)

__device__ __half g_KH[NELEM];
__device__ __half g_VH[NELEM];
__device__ int    g_anyMask;

#define ONES 0x3C003C00u

__device__ __forceinline__ uint32_t pkh2(float lo, float hi) {
    uint32_t r; asm("cvt.rn.f16x2.f32 %0, %2, %1;" : "=r"(r) : "f"(lo), "f"(hi)); return r;
}
__device__ __forceinline__ uint32_t ex2h2(uint32_t h) {
    uint32_t r; asm("ex2.approx.f16x2 %0, %1;" : "=r"(r) : "r"(h)); return r;
}
__device__ __forceinline__ void ldsm4(uint32_t a, uint32_t d[4]) {
    asm volatile("ldmatrix.sync.aligned.m8n8.x4.shared.b16 {%0,%1,%2,%3}, [%4];"
                 : "=r"(d[0]), "=r"(d[1]), "=r"(d[2]), "=r"(d[3]) : "r"(a));
}
__device__ __forceinline__ void ldsm4t(uint32_t a, uint32_t d[4]) {
    asm volatile("ldmatrix.sync.aligned.m8n8.x4.trans.shared.b16 {%0,%1,%2,%3}, [%4];"
                 : "=r"(d[0]), "=r"(d[1]), "=r"(d[2]), "=r"(d[3]) : "r"(a));
}
__device__ __forceinline__ void mma16(float d[4], const uint32_t a[4],
                                      uint32_t b0, uint32_t b1) {
    asm volatile("mma.sync.aligned.m16n8k16.row.col.f32.f16.f16.f32 "
                 "{%0,%1,%2,%3}, {%4,%5,%6,%7}, {%8,%9}, {%0,%1,%2,%3};"
                 : "+f"(d[0]), "+f"(d[1]), "+f"(d[2]), "+f"(d[3])
                 : "r"(a[0]), "r"(a[1]), "r"(a[2]), "r"(a[3]), "r"(b0), "r"(b1));
}
__device__ __forceinline__ void mma16h(uint32_t d[2], const uint32_t a[4],
                                       uint32_t b0, uint32_t b1) {
    asm volatile("mma.sync.aligned.m16n8k16.row.col.f16.f16.f16.f16 "
                 "{%0,%1}, {%2,%3,%4,%5}, {%6,%7}, {%0,%1};"
                 : "+r"(d[0]), "+r"(d[1])
                 : "r"(a[0]), "r"(a[1]), "r"(a[2]), "r"(a[3]), "r"(b0), "r"(b1));
}

// ---- fused pre-pass: K,V fp32->fp16 + mask any-scan (blocks 0..1023 scan mask)
__global__ __launch_bounds__(256)
void cvt_kv_scan_kernel(const float* __restrict__ K, const float* __restrict__ V,
                        const unsigned char* __restrict__ M)
{
    const int i = blockIdx.x * 256 + threadIdx.x;
    const int half_sel = i >> 20;                 // NELEM/4 = 1048576
    const int j = i & 1048575;
    const float4 v = ((const float4*)(half_sel ? V : K))[j];
    uint2 o; o.x = pkh2(v.x, v.y); o.y = pkh2(v.z, v.w);
    ((uint2*)(half_sel ? g_VH : g_KH))[j] = o;

    if (blockIdx.x < 1024) {                      // 1024*256*16B = 4MB mask
        const uint4 m = ((const uint4*)M)[blockIdx.x * 256 + threadIdx.x];
        int any = ((m.x | m.y | m.z | m.w) != 0u);
        if (__syncthreads_or(any)) {
            if (threadIdx.x == 0) atomicOr(&g_anyMask, 1);
        }
    }
}

__global__ __launch_bounds__(64, 4)
void attn_h16m_kernel(const float* __restrict__ Q, const unsigned char* __restrict__ M,
                      float* __restrict__ Out)
{
    extern __shared__ __half smh[];
    const uint32_t sb = (uint32_t)__cvta_generic_to_shared(smh);

    const int t = threadIdx.x, lane = t & 31, w = t >> 5;   // w in {0,1}
    const int g = lane >> 2, c = lane & 3;
    const int mb = blockIdx.x & 31, bh = blockIdx.x >> 5;   // S/BM = 32
    const size_t head = (size_t)bh * SEQ * DH;

    const int mi = lane >> 3, lr = lane & 7;
    const uint32_t koff = (uint32_t)(((mi >> 1) * 8 + lr) * SH + (mi & 1) * 8);
    const uint32_t voff = (uint32_t)(((mi & 1) * 8 + lr) * SH + (mi >> 1) * 8);

    const float Cc = 0.022097086912079608f * 1.4426950408889634f; // scale*log2e
    const bool flag = (g_anyMask != 0);

    // ---- stage Q (fp16, pre-scaled by Cc) through K0 region (64 rows)
    {
        const float* Qg = Q + head + (size_t)(mb * BM + t) * DH;
        __half* qd = smh + (size_t)t * SH;
        #pragma unroll
        for (int u = 0; u < 8; u++) {
            float4 a = ((const float4*)Qg)[2*u], b = ((const float4*)Qg)[2*u+1];
            uint4 s;
            s.x = pkh2(a.x * Cc, a.y * Cc); s.y = pkh2(a.z * Cc, a.w * Cc);
            s.z = pkh2(b.x * Cc, b.y * Cc); s.w = pkh2(b.z * Cc, b.w * Cc);
            *(uint4*)(qd + u * 8) = s;
        }
    }
    __syncthreads();
    uint32_t qf[2][4][4];                 // [m-tile][k-step][frag]
    #pragma unroll
    for (int mt = 0; mt < 2; mt++)
        #pragma unroll
        for (int ks = 0; ks < 4; ks++)
            ldsm4(sb + (uint32_t)((w*32 + mt*16 + (mi&1)*8 + lr) * SH
                                  + (mi>>1)*8 + ks*16) * 2, qf[mt][ks]);
    __syncthreads();   // qf done before tile-0 cp.async reuses K0

    // cp.async loader: 64 threads, thread t -> K row t and V row t (8x16B each)
    auto issueTile = [&](int nt, int buf) {
        const __half* Kg = g_KH + head + (size_t)(nt * BN + t) * DH;
        const __half* Vg = g_VH + head + (size_t)(nt * BN + t) * DH;
        uint32_t kd = sb + (uint32_t)((buf ? K1H : K0H) + t * SH) * 2;
        uint32_t vd = sb + (uint32_t)((buf ? V1H : V0H) + t * SH) * 2;
        #pragma unroll
        for (int i = 0; i < 8; i++)
            asm volatile("cp.async.cg.shared.global [%0], [%1], 16;"
                         :: "r"(kd + i * 16), "l"(Kg + i * 8) : "memory");
        #pragma unroll
        for (int i = 0; i < 8; i++)
            asm volatile("cp.async.cg.shared.global [%0], [%1], 16;"
                         :: "r"(vd + i * 16), "l"(Vg + i * 8) : "memory");
        asm volatile("cp.async.commit_group;" ::: "memory");
    };

    float oacc[2][8][4];
    #pragma unroll
    for (int mt = 0; mt < 2; mt++)
        #pragma unroll
        for (int i = 0; i < 8; i++)
            #pragma unroll
            for (int j = 0; j < 4; j++) oacc[mt][i][j] = 0.0f;
    float lacc[2][2][4];
    #pragma unroll
    for (int s = 0; s < 2; s++)
        #pragma unroll
        for (int mt = 0; mt < 2; mt++)
            #pragma unroll
            for (int j = 0; j < 4; j++) lacc[s][mt][j] = 0.0f;

    issueTile(0, 0);
    asm volatile("cp.async.wait_group 0;" ::: "memory");
    __syncthreads();

    #pragma unroll 1
    for (int nt = 0; nt < NT; nt++) {
        const int buf = nt & 1;
        const bool more = (nt + 1) < NT;
        if (more) issueTile(nt + 1, buf ^ 1);

        // ---- MMA1: S = Q K^T, fp16 accum (ks outer)
        const uint32_t kb = sb + ((buf ? K1H : K0H) + koff) * 2;
        uint32_t sacc[2][8][2];
        #pragma unroll
        for (int mt = 0; mt < 2; mt++)
            #pragma unroll
            for (int i = 0; i < 8; i++) { sacc[mt][i][0] = 0u; sacc[mt][i][1] = 0u; }
        #pragma unroll
        for (int ks = 0; ks < 4; ks++) {
            #pragma unroll
            for (int np = 0; np < 4; np++) {
                uint32_t b[4];
                ldsm4(kb + (uint32_t)(np * 16 * SH + ks * 16) * 2, b);
                #pragma unroll
                for (int mt = 0; mt < 2; mt++) {
                    mma16h(sacc[mt][2*np],     qf[mt][ks], b[0], b[1]);
                    mma16h(sacc[mt][2*np + 1], qf[mt][ks], b[2], b[3]);
                }
            }
        }

        // ---- mask slow path (never taken for all-False mask)
        if (flag) {
            #pragma unroll
            for (int mt = 0; mt < 2; mt++) {
                const int r0 = mb * BM + w * 32 + mt * 16 + g;
                const unsigned char* q0 = M + (size_t)r0 * SEQ + nt * BN;
                const unsigned char* q1 = q0 + 8 * SEQ;
                #pragma unroll
                for (int n = 0; n < 8; n++) {
                    int c0 = 8 * n + 2 * c;
                    if (q0[c0    ]) sacc[mt][n][0] = (sacc[mt][n][0] & 0xFFFF0000u) | 0x0000FC00u;
                    if (q0[c0 + 1]) sacc[mt][n][0] = (sacc[mt][n][0] & 0x0000FFFFu) | 0xFC000000u;
                    if (q1[c0    ]) sacc[mt][n][1] = (sacc[mt][n][1] & 0xFFFF0000u) | 0x0000FC00u;
                    if (q1[c0 + 1]) sacc[mt][n][1] = (sacc[mt][n][1] & 0x0000FFFFu) | 0xFC000000u;
                }
            }
        }

        // ---- softmax numerator on f16x2 fragments; row sums via ones-MMA
        uint32_t paf[2][4][4];
        #pragma unroll
        for (int mt = 0; mt < 2; mt++) {
            #pragma unroll
            for (int np = 0; np < 4; np++) {
                paf[mt][np][0] = ex2h2(sacc[mt][2*np    ][0]);
                paf[mt][np][1] = ex2h2(sacc[mt][2*np    ][1]);
                paf[mt][np][2] = ex2h2(sacc[mt][2*np + 1][0]);
                paf[mt][np][3] = ex2h2(sacc[mt][2*np + 1][1]);
                mma16(lacc[np & 1][mt], paf[mt][np], ONES, ONES);
            }
        }

        // ---- MMA2: O += P V, f32 accum (ks outer)
        const uint32_t vb = sb + ((buf ? V1H : V0H) + voff) * 2;
        #pragma unroll
        for (int ks = 0; ks < 4; ks++) {
            #pragma unroll
            for (int dnp = 0; dnp < 4; dnp++) {
                uint32_t b[4];
                ldsm4t(vb + (uint32_t)(ks * 16 * SH + dnp * 16) * 2, b);
                #pragma unroll
                for (int mt = 0; mt < 2; mt++) {
                    mma16(oacc[mt][2*dnp],     paf[mt][ks], b[0], b[1]);
                    mma16(oacc[mt][2*dnp + 1], paf[mt][ks], b[2], b[3]);
                }
            }
        }

        if (more) {
            asm volatile("cp.async.wait_group 0;" ::: "memory");
            __syncthreads();
        }
    }

    // ---- epilogue: O / l   (l = lacc0 + lacc1; frag 0 = row g, frag 2 = row g+8)
    #pragma unroll
    for (int mt = 0; mt < 2; mt++) {
        const int r0 = mb * BM + w * 32 + mt * 16 + g;
        float* O0 = Out + head + (size_t)r0 * DH;
        float* O1 = O0 + 8 * DH;
        const float inv0 = 1.0f / (lacc[0][mt][0] + lacc[1][mt][0]);
        const float inv1 = 1.0f / (lacc[0][mt][2] + lacc[1][mt][2]);
        #pragma unroll
        for (int dn = 0; dn < 8; dn++) {
            float2 w0, w1;
            w0.x = oacc[mt][dn][0] * inv0; w0.y = oacc[mt][dn][1] * inv0;
            w1.x = oacc[mt][dn][2] * inv1; w1.y = oacc[mt][dn][3] * inv1;
            *(float2*)(O0 + 8*dn + 2*c) = w0;
            *(float2*)(O1 + 8*dn + 2*c) = w1;
        }
    }
}

extern "C" void kernel_launch(void* const* d_in, const int* in_sizes, int n_in,
                              void* d_out, int out_size)
{
    const float* Q = (const float*)d_in[0];
    const float* K = (const float*)d_in[1];
    const float* V = (const float*)d_in[2];
    const unsigned char* mask = (const unsigned char*)d_in[3];
    float* Out = (float*)d_out;

    // zero the mask flag (no alloc; async memset is graph-capturable)
    void* flagAddr = nullptr;
    cudaGetSymbolAddress(&flagAddr, g_anyMask);
    cudaMemsetAsync(flagAddr, 0, sizeof(int));

    cvt_kv_scan_kernel<<<8192, 256>>>(K, V, mask);

    cudaFuncSetAttribute(attn_h16m_kernel,
                         cudaFuncAttributeMaxDynamicSharedMemorySize, SMEM_BYTES);
    // grid = (B*H)=32 x (S/BM)=32 = 1024 CTAs of 64 threads
    attn_h16m_kernel<<<1024, 64, SMEM_BYTES>>>(Q, mask, Out);
}

// round 16
// speedup vs baseline: 1.4237x; 1.4237x over previous
#include <cuda_runtime.h>
#include <cuda_fp16.h>
#include <cstdint>

// B=2,H=16,S=2048,D=64 fp32 attention; scale=1/sqrt(2048) AFTER masked_fill(-1e10).
// Logits bounded -> exp without max-subtraction; masked -> p=0.
// Round 16: main kernel = R12 champion (untouched). Pre-pass consolidated:
//   - g_anyMask zeroed via cudaMemsetAsync (no init kernel launch)
//   - mask any-scan fused into the K/V fp16 convert kernel (no scan launch)
#define SEQ 2048
#define DH  64
#define BM  128
#define BN  64
#define NT  (SEQ/BN)
#define SH  72

#define K0H 0
#define K1H (64*SH)
#define V0H (2*64*SH)
#define V1H (3*64*SH)
#define SMEM_BYTES (4*64*SH*2)

#define NELEM (2*16*2048*64)

__device__ __half g_KH[NELEM];
__device__ __half g_VH[NELEM];
__device__ int    g_anyMask;

#define ONES 0x3C003C00u

__device__ __forceinline__ uint32_t pkh2(float lo, float hi) {
    uint32_t r; asm("cvt.rn.f16x2.f32 %0, %2, %1;" : "=r"(r) : "f"(lo), "f"(hi)); return r;
}
__device__ __forceinline__ uint32_t ex2h2(uint32_t h) {
    uint32_t r; asm("ex2.approx.f16x2 %0, %1;" : "=r"(r) : "r"(h)); return r;
}
__device__ __forceinline__ void ldsm4(uint32_t a, uint32_t d[4]) {
    asm volatile("ldmatrix.sync.aligned.m8n8.x4.shared.b16 {%0,%1,%2,%3}, [%4];"
                 : "=r"(d[0]), "=r"(d[1]), "=r"(d[2]), "=r"(d[3]) : "r"(a));
}
__device__ __forceinline__ void ldsm4t(uint32_t a, uint32_t d[4]) {
    asm volatile("ldmatrix.sync.aligned.m8n8.x4.trans.shared.b16 {%0,%1,%2,%3}, [%4];"
                 : "=r"(d[0]), "=r"(d[1]), "=r"(d[2]), "=r"(d[3]) : "r"(a));
}
__device__ __forceinline__ void mma16(float d[4], const uint32_t a[4],
                                      uint32_t b0, uint32_t b1) {
    asm volatile("mma.sync.aligned.m16n8k16.row.col.f32.f16.f16.f32 "
                 "{%0,%1,%2,%3}, {%4,%5,%6,%7}, {%8,%9}, {%0,%1,%2,%3};"
                 : "+f"(d[0]), "+f"(d[1]), "+f"(d[2]), "+f"(d[3])
                 : "r"(a[0]), "r"(a[1]), "r"(a[2]), "r"(a[3]), "r"(b0), "r"(b1));
}
__device__ __forceinline__ void mma16h(uint32_t d[2], const uint32_t a[4],
                                       uint32_t b0, uint32_t b1) {
    asm volatile("mma.sync.aligned.m16n8k16.row.col.f16.f16.f16.f16 "
                 "{%0,%1}, {%2,%3,%4,%5}, {%6,%7}, {%0,%1};"
                 : "+r"(d[0]), "+r"(d[1])
                 : "r"(a[0]), "r"(a[1]), "r"(a[2]), "r"(a[3]), "r"(b0), "r"(b1));
}

// ---- fused pre-pass: K,V fp32->fp16 convert + mask any-scan (first 1024 blocks)
__global__ __launch_bounds__(256)
void cvt_kv_scan_kernel(const float* __restrict__ K, const float* __restrict__ V,
                        const unsigned char* __restrict__ M)
{
    const int i = blockIdx.x * 256 + threadIdx.x;
    const int half_sel = i >> 20;                 // NELEM/4 = 1048576
    const int j = i & 1048575;
    const float4 v = ((const float4*)(half_sel ? V : K))[j];
    uint2 o; o.x = pkh2(v.x, v.y); o.y = pkh2(v.z, v.w);
    ((uint2*)(half_sel ? g_VH : g_KH))[j] = o;

    if (blockIdx.x < 1024) {                      // 1024*256*16B = 4MB mask
        const uint4 m = ((const uint4*)M)[blockIdx.x * 256 + threadIdx.x];
        int any = ((m.x | m.y | m.z | m.w) != 0u);
        if (__syncthreads_or(any)) {
            if (threadIdx.x == 0) atomicOr(&g_anyMask, 1);
        }
    }
}

// ---- main kernel: identical to R12 champion
__global__ __launch_bounds__(128, 2)
void attn_h16n_kernel(const float* __restrict__ Q, const unsigned char* __restrict__ M,
                      float* __restrict__ Out)
{
    extern __shared__ __half smh[];
    const uint32_t sb = (uint32_t)__cvta_generic_to_shared(smh);

    const int t = threadIdx.x, lane = t & 31, w = t >> 5;
    const int g = lane >> 2, c = lane & 3;
    const int mb = blockIdx.x & 15, bh = blockIdx.x >> 4;
    const size_t head = (size_t)bh * SEQ * DH;

    const int mi = lane >> 3, lr = lane & 7;
    const uint32_t koff = (uint32_t)(((mi >> 1) * 8 + lr) * SH + (mi & 1) * 8);
    const uint32_t voff = (uint32_t)(((mi & 1) * 8 + lr) * SH + (mi >> 1) * 8);

    const float Cc = 0.022097086912079608f * 1.4426950408889634f; // scale*log2e
    const bool flag = (g_anyMask != 0);

    // ---- stage Q (fp16, pre-scaled by Cc), build persistent A fragments
    {
        const float* Qg = Q + head + (size_t)(mb * BM + t) * DH;
        __half* qd = smh + (size_t)t * SH;
        #pragma unroll
        for (int u = 0; u < 8; u++) {
            float4 a = ((const float4*)Qg)[2*u], b = ((const float4*)Qg)[2*u+1];
            uint4 s;
            s.x = pkh2(a.x * Cc, a.y * Cc); s.y = pkh2(a.z * Cc, a.w * Cc);
            s.z = pkh2(b.x * Cc, b.y * Cc); s.w = pkh2(b.z * Cc, b.w * Cc);
            *(uint4*)(qd + u * 8) = s;
        }
    }
    __syncthreads();
    uint32_t qf[2][4][4];
    #pragma unroll
    for (int mt = 0; mt < 2; mt++)
        #pragma unroll
        for (int ks = 0; ks < 4; ks++)
            ldsm4(sb + (uint32_t)((w*32 + mt*16 + (mi&1)*8 + lr) * SH
                                  + (mi>>1)*8 + ks*16) * 2, qf[mt][ks]);
    __syncthreads();

    const int trow = t >> 1, tcol = (t & 1) * 32;
    auto issueTile = [&](int nt, int buf) {
        const __half* Kg = g_KH + head + (size_t)(nt * BN + trow) * DH + tcol;
        const __half* Vg = g_VH + head + (size_t)(nt * BN + trow) * DH + tcol;
        uint32_t kd = sb + (uint32_t)((buf ? K1H : K0H) + trow * SH + tcol) * 2;
        uint32_t vd = sb + (uint32_t)((buf ? V1H : V0H) + trow * SH + tcol) * 2;
        #pragma unroll
        for (int i = 0; i < 4; i++)
            asm volatile("cp.async.cg.shared.global [%0], [%1], 16;"
                         :: "r"(kd + i * 16), "l"(Kg + i * 8) : "memory");
        #pragma unroll
        for (int i = 0; i < 4; i++)
            asm volatile("cp.async.cg.shared.global [%0], [%1], 16;"
                         :: "r"(vd + i * 16), "l"(Vg + i * 8) : "memory");
        asm volatile("cp.async.commit_group;" ::: "memory");
    };

    float oacc[2][8][4];
    #pragma unroll
    for (int mt = 0; mt < 2; mt++)
        #pragma unroll
        for (int i = 0; i < 8; i++)
            #pragma unroll
            for (int j = 0; j < 4; j++) oacc[mt][i][j] = 0.0f;
    float lacc[2][2][4];
    #pragma unroll
    for (int s = 0; s < 2; s++)
        #pragma unroll
        for (int mt = 0; mt < 2; mt++)
            #pragma unroll
            for (int j = 0; j < 4; j++) lacc[s][mt][j] = 0.0f;

    issueTile(0, 0);
    asm volatile("cp.async.wait_group 0;" ::: "memory");
    __syncthreads();

    #pragma unroll 1
    for (int nt = 0; nt < NT; nt++) {
        const int buf = nt & 1;
        const bool more = (nt + 1) < NT;
        if (more) issueTile(nt + 1, buf ^ 1);

        // ---- MMA1: S = Q K^T, fp16 accum (ks outer)
        const uint32_t kb = sb + ((buf ? K1H : K0H) + koff) * 2;
        uint32_t sacc[2][8][2];
        #pragma unroll
        for (int mt = 0; mt < 2; mt++)
            #pragma unroll
            for (int i = 0; i < 8; i++) { sacc[mt][i][0] = 0u; sacc[mt][i][1] = 0u; }
        #pragma unroll
        for (int ks = 0; ks < 4; ks++) {
            #pragma unroll
            for (int np = 0; np < 4; np++) {
                uint32_t b[4];
                ldsm4(kb + (uint32_t)(np * 16 * SH + ks * 16) * 2, b);
                #pragma unroll
                for (int mt = 0; mt < 2; mt++) {
                    mma16h(sacc[mt][2*np],     qf[mt][ks], b[0], b[1]);
                    mma16h(sacc[mt][2*np + 1], qf[mt][ks], b[2], b[3]);
                }
            }
        }

        // ---- mask slow path (never taken for all-False mask)
        if (flag) {
            #pragma unroll
            for (int mt = 0; mt < 2; mt++) {
                const int r0 = mb * BM + w * 32 + mt * 16 + g;
                const unsigned char* q0 = M + (size_t)r0 * SEQ + nt * BN;
                const unsigned char* q1 = q0 + 8 * SEQ;
                #pragma unroll
                for (int n = 0; n < 8; n++) {
                    int c0 = 8 * n + 2 * c;
                    if (q0[c0    ]) sacc[mt][n][0] = (sacc[mt][n][0] & 0xFFFF0000u) | 0x0000FC00u;
                    if (q0[c0 + 1]) sacc[mt][n][0] = (sacc[mt][n][0] & 0x0000FFFFu) | 0xFC000000u;
                    if (q1[c0    ]) sacc[mt][n][1] = (sacc[mt][n][1] & 0xFFFF0000u) | 0x0000FC00u;
                    if (q1[c0 + 1]) sacc[mt][n][1] = (sacc[mt][n][1] & 0x0000FFFFu) | 0xFC000000u;
                }
            }
        }

        // ---- softmax numerator: p = exp2(s) directly on f16x2 fragments
        uint32_t paf[2][4][4];
        #pragma unroll
        for (int mt = 0; mt < 2; mt++) {
            #pragma unroll
            for (int np = 0; np < 4; np++) {
                paf[mt][np][0] = ex2h2(sacc[mt][2*np    ][0]);
                paf[mt][np][1] = ex2h2(sacc[mt][2*np    ][1]);
                paf[mt][np][2] = ex2h2(sacc[mt][2*np + 1][0]);
                paf[mt][np][3] = ex2h2(sacc[mt][2*np + 1][1]);
                mma16(lacc[np & 1][mt], paf[mt][np], ONES, ONES);   // row sums
            }
        }

        // ---- MMA2: O += P V (f32 accum; ks outer)
        const uint32_t vb = sb + ((buf ? V1H : V0H) + voff) * 2;
        #pragma unroll
        for (int ks = 0; ks < 4; ks++) {
            #pragma unroll
            for (int dnp = 0; dnp < 4; dnp++) {
                uint32_t b[4];
                ldsm4t(vb + (uint32_t)(ks * 16 * SH + dnp * 16) * 2, b);
                #pragma unroll
                for (int mt = 0; mt < 2; mt++) {
                    mma16(oacc[mt][2*dnp],     paf[mt][ks], b[0], b[1]);
                    mma16(oacc[mt][2*dnp + 1], paf[mt][ks], b[2], b[3]);
                }
            }
        }

        if (more) {
            asm volatile("cp.async.wait_group 0;" ::: "memory");
            __syncthreads();
        }
    }

    // ---- epilogue: O / l   (l = lacc0 + lacc1; frag 0 = row g, frag 2 = row g+8)
    #pragma unroll
    for (int mt = 0; mt < 2; mt++) {
        const int r0 = mb * BM + w * 32 + mt * 16 + g;
        float* O0 = Out + head + (size_t)r0 * DH;
        float* O1 = O0 + 8 * DH;
        const float inv0 = 1.0f / (lacc[0][mt][0] + lacc[1][mt][0]);
        const float inv1 = 1.0f / (lacc[0][mt][2] + lacc[1][mt][2]);
        #pragma unroll
        for (int dn = 0; dn < 8; dn++) {
            float2 w0, w1;
            w0.x = oacc[mt][dn][0] * inv0; w0.y = oacc[mt][dn][1] * inv0;
            w1.x = oacc[mt][dn][2] * inv1; w1.y = oacc[mt][dn][3] * inv1;
            *(float2*)(O0 + 8*dn + 2*c) = w0;
            *(float2*)(O1 + 8*dn + 2*c) = w1;
        }
    }
}

extern "C" void kernel_launch(void* const* d_in, const int* in_sizes, int n_in,
                              void* d_out, int out_size)
{
    const float* Q = (const float*)d_in[0];
    const float* K = (const float*)d_in[1];
    const float* V = (const float*)d_in[2];
    const unsigned char* mask = (const unsigned char*)d_in[3];
    float* Out = (float*)d_out;

    // zero the mask flag (async memset on a __device__ symbol: no alloc,
    // graph-capturable)
    void* flagAddr = nullptr;
    cudaGetSymbolAddress(&flagAddr, g_anyMask);
    cudaMemsetAsync(flagAddr, 0, sizeof(int));

    // fused pre-pass: fp16 convert of K,V + mask any-scan
    cvt_kv_scan_kernel<<<8192, 256>>>(K, V, mask);

    cudaFuncSetAttribute(attn_h16n_kernel,
                         cudaFuncAttributeMaxDynamicSharedMemorySize, SMEM_BYTES);
    // grid = (B*H)=32 x (S/BM)=16
    attn_h16n_kernel<<<512, 128, SMEM_BYTES>>>(Q, mask, Out);
}